// round 8
// baseline (speedup 1.0000x reference)
#include <cuda_runtime.h>
#include <math.h>
#include <stdint.h>

// Problem constants
#define B_   512
#define T_   200
#define D_   256
#define H_   256
#define BT_  (B_ * T_)      // 102400

// Recurrent-kernel geometry
#define RG_  16             // batch rows per cluster
#define NG_  (B_ / RG_)     // 32 clusters
#define CSZ  4              // CTAs per cluster (column split)
#define THREADS_R 512

typedef unsigned long long ull;

// Scratch (device globals; no allocation anywhere)
__device__ float g_Gx[BT_ * 2 * H_];   // [B*T, 512]  x@Wgx + gate_bias
__device__ float g_Cx[BT_ * H_];       // [B*T, 256]  x@Wcx + cand_bias

// SMEM layout (float offsets)
#define OFF_WG 0            // [64 kb][128 jcol][4 k]  (128 KB)
#define OFF_WC 32768        // [64 kb][64 j][4 k] padded kb-stride 264 (66 KB)
#define WCSTR  264
#define OFF_H  49664        // h[row 16][k 256], XOR-swizzled (16 KB)
#define OFF_U  53760        // u[j 64][row 16] (4 KB)
#define SMEM_FLOATS 54784
#define SMEM_BYTES (SMEM_FLOATS * 4)   // 219136 B

// h swizzle: row group (row>>2) XORs k by {0,8,16,24} floats -> 16B chunks of
// the 4 rows in one LSU phase land in disjoint bank quartets. Self-inverse.
// 4-aligned k stays contiguous (XOR bits >= 8 floats).
__device__ __forceinline__ int hoff(int row, int k) {
    return row * 256 + (k ^ (((row >> 2) & 3) << 3));
}

// ---- Blackwell packed fp32x2 helpers ----
__device__ __forceinline__ ull fma2(ull a, ull b, ull c) {
    ull d; asm("fma.rn.f32x2 %0, %1, %2, %3;" : "=l"(d) : "l"(a), "l"(b), "l"(c));
    return d;
}
__device__ __forceinline__ ull pack2(float lo, float hi) {
    ull d; asm("mov.b64 %0, {%1, %2};" : "=l"(d) : "f"(lo), "f"(hi));
    return d;
}
__device__ __forceinline__ float2 unpack2(ull v) {
    float2 r; asm("mov.b64 {%0, %1}, %2;" : "=f"(r.x), "=f"(r.y) : "l"(v));
    return r;
}
__device__ __forceinline__ float sigmoid_f(float x) { return 1.f / (1.f + __expf(-x)); }
__device__ __forceinline__ float tanh_f(float x)    { return 2.f / (1.f + __expf(-2.f * x)) - 1.f; }

__device__ __forceinline__ uint32_t smem_u32(const void* p) {
    uint32_t a;
    asm("{ .reg .u64 t; cvta.to.shared.u64 t, %1; cvt.u32.u64 %0, t; }" : "=r"(a) : "l"(p));
    return a;
}
__device__ __forceinline__ uint32_t ctarank() {
    uint32_t r; asm("mov.u32 %0, %%cluster_ctarank;" : "=r"(r));
    return r;
}
__device__ __forceinline__ uint32_t mapa_sh(uint32_t addr, uint32_t rank) {
    uint32_t r; asm("mapa.shared::cluster.u32 %0, %1, %2;" : "=r"(r) : "r"(addr), "r"(rank));
    return r;
}
__device__ __forceinline__ void st_cluster_b64(uint32_t addr, ull v) {
    asm volatile("st.shared::cluster.b64 [%0], %1;" :: "r"(addr), "l"(v) : "memory");
}
#define CLUSTER_SYNC() do { \
    asm volatile("barrier.cluster.arrive.aligned;" ::: "memory"); \
    asm volatile("barrier.cluster.wait.aligned;" ::: "memory");   \
} while (0)

// ---------------------------------------------------------------------------
// Precompute GEMM (unchanged; ~40 TF/s effective)
// ---------------------------------------------------------------------------
#define GBM 128
#define GBN 64
#define GBK 16

__global__ __launch_bounds__(256) void gemm_precompute(
    const float* __restrict__ X,
    const float* __restrict__ W,
    const float* __restrict__ bias,
    const int*   __restrict__ seqlen,
    int N)
{
    const int r0 = blockIdx.x * GBM;
    const int n0 = blockIdx.y * GBN;

    {
        int b0 = r0 / T_;
        int b1 = (r0 + GBM - 1) / T_;
        bool needed = false;
        for (int b = b0; b <= b1; ++b) {
            int tstart = r0 - b * T_;
            if (tstart < 0) tstart = 0;
            if (tstart < seqlen[b]) { needed = true; break; }
        }
        if (!needed) return;
    }

    float* __restrict__ C = (N == 2 * H_) ? g_Gx : g_Cx;

    __shared__ float As[GBK][GBM];
    __shared__ float Bs[GBK][GBN];

    const int tid = threadIdx.x;
    const int am  = tid >> 2;
    const int ak  = (tid & 3) * 4;
    const int bk  = tid >> 4;
    const int bn  = (tid & 15) * 4;
    const int tm  = (tid >> 4) * 8;
    const int tn  = (tid & 15) * 4;

    ull acc2[4][4];
#pragma unroll
    for (int p = 0; p < 4; ++p)
#pragma unroll
        for (int j = 0; j < 4; ++j) acc2[p][j] = 0ull;

    for (int kt = 0; kt < D_; kt += GBK) {
        float4 a0 = *(const float4*)(X + (size_t)(r0 + am) * D_ + kt + ak);
        float4 a1 = *(const float4*)(X + (size_t)(r0 + am + 64) * D_ + kt + ak);
        As[ak + 0][am] = a0.x;  As[ak + 1][am] = a0.y;
        As[ak + 2][am] = a0.z;  As[ak + 3][am] = a0.w;
        As[ak + 0][am + 64] = a1.x;  As[ak + 1][am + 64] = a1.y;
        As[ak + 2][am + 64] = a1.z;  As[ak + 3][am + 64] = a1.w;
        *(float4*)&Bs[bk][bn] = *(const float4*)(W + (size_t)(kt + bk) * N + n0 + bn);
        __syncthreads();

#pragma unroll
        for (int k = 0; k < GBK; ++k) {
            ulonglong2 a01 = *(const ulonglong2*)&As[k][tm];
            ulonglong2 a23 = *(const ulonglong2*)&As[k][tm + 4];
            float4 bq = *(const float4*)&Bs[k][tn];
            ull ap[4] = { a01.x, a01.y, a23.x, a23.y };
            ull bp[4] = { pack2(bq.x, bq.x), pack2(bq.y, bq.y),
                          pack2(bq.z, bq.z), pack2(bq.w, bq.w) };
#pragma unroll
            for (int p = 0; p < 4; ++p)
#pragma unroll
                for (int j = 0; j < 4; ++j)
                    acc2[p][j] = fma2(ap[p], bp[j], acc2[p][j]);
        }
        __syncthreads();
    }

    float4 bv = *(const float4*)(bias + n0 + tn);
#pragma unroll
    for (int p = 0; p < 4; ++p) {
        float2 c0 = unpack2(acc2[p][0]);
        float2 c1 = unpack2(acc2[p][1]);
        float2 c2 = unpack2(acc2[p][2]);
        float2 c3 = unpack2(acc2[p][3]);
        int row0 = r0 + tm + 2 * p;
        float4 o0 = make_float4(c0.x + bv.x, c1.x + bv.y, c2.x + bv.z, c3.x + bv.w);
        float4 o1 = make_float4(c0.y + bv.x, c1.y + bv.y, c2.y + bv.z, c3.y + bv.w);
        *(float4*)(C + (size_t)row0 * N + n0 + tn) = o0;
        *(float4*)(C + (size_t)(row0 + 1) * N + n0 + tn) = o1;
    }
}

// ---------------------------------------------------------------------------
// Recurrent kernel: 32 clusters x 4 CTAs, 16 batch rows/cluster, weights in
// SMEM. 2-D register blocking (4 cols x 4 rows per thread) + k-split so every
// LDS.128 feeds 32/8 fma2 -> wavefront-bound cost drops ~2.4x vs round 6.
// Phase1: lane = ks(2)<<3 | cg(1)<<2 | rg(2); warp w covers gate cols
//   [w*8, w*8+8) (w<8: r-cols, w>=8: u-cols), rows rg*4..+3, k-quarter ks.
// Phase2: lane = ks(3)<<2 | rg(2); warp w covers cand cols [w*4, w*4+4),
//   rows rg*4..+3, k-eighth ks. k-partials reduced via shfl.bfly.
// ---------------------------------------------------------------------------
__global__ __launch_bounds__(THREADS_R, 1) __cluster_dims__(CSZ, 1, 1)
void gru_recurrent(const float* __restrict__ Wg,   // [512, 512]
                   const float* __restrict__ Wc,   // [512, 256]
                   const int*   __restrict__ seqlen,
                   float* __restrict__ out)        // [B, T, 256]
{
    extern __shared__ float sm[];
    const int tid  = threadIdx.x;
    const int lane = tid & 31;
    const int warp = tid >> 5;
    const uint32_t c = ctarank();
    const int b0 = (blockIdx.x / CSZ) * RG_;

    // phase-1 mapping
    const int p1_rg = lane & 3;
    const int p1_cg = (lane >> 2) & 1;
    const int p1_ks = lane >> 3;
    const int p1_jb = warp * 8 + p1_cg * 4;           // 0..124 (gate col base)
    const bool isRw = (warp < 8);
    const int gcolb = isRw ? ((int)c * 64 + p1_jb)
                           : (256 + (int)c * 64 + (p1_jb - 64));
    const int hcolb = (int)c * 64 + p1_jb;            // valid for r-warps

    // phase-2 mapping
    const int p2_rg = lane & 3;
    const int p2_ks = lane >> 2;
    const int p2_jb = warp * 4;                       // 0..60 (cand col base)
    const int gc2   = (int)c * 64 + p2_jb;
    const bool isOut = (lane < 4);                    // p2_ks==0 lanes

    // ---- load weight slices into SMEM ----
    for (int idx = tid; idx < 64 * 128; idx += THREADS_R) {
        int kb = idx >> 7, jj = idx & 127;
        int col = (jj < 64) ? ((int)c * 64 + jj) : (256 + (int)c * 64 + (jj - 64));
#pragma unroll
        for (int i = 0; i < 4; ++i)
            sm[OFF_WG + kb * 512 + jj * 4 + i] = Wg[(256 + kb * 4 + i) * 512 + col];
    }
    for (int idx = tid; idx < 64 * 64; idx += THREADS_R) {
        int kb = idx >> 6, jj = idx & 63;
        int col = (int)c * 64 + jj;
#pragma unroll
        for (int i = 0; i < 4; ++i)
            sm[OFF_WC + kb * WCSTR + jj * 4 + i] = Wc[(256 + kb * 4 + i) * 256 + col];
    }
    for (int i = tid; i < 16 * 256; i += THREADS_R) sm[OFF_H + i] = 0.f;

    int tmax = 0;
    for (int rr = 0; rr < RG_; ++rr) tmax = max(tmax, seqlen[b0 + rr]);
    int lenv[4];
#pragma unroll
    for (int ri = 0; ri < 4; ++ri)
        lenv[ri] = isOut ? seqlen[b0 + lane * 4 + ri] : 0;

    __syncthreads();
    CLUSTER_SYNC();

    const uint32_t smaddr = smem_u32(sm);
    const int p1_swz = p1_rg << 3;
    const int p2_swz = p2_rg << 3;

    for (int t = 0; t < tmax; ++t) {
        // ================= phase 1 GEMV (gates) =================
        ull a[16];
#pragma unroll
        for (int x = 0; x < 16; ++x) a[x] = 0ull;
        {
            const float* wgp = sm + OFF_WG + p1_jb * 4;
            const float* hb  = sm + OFF_H + p1_rg * 4 * 256;
#pragma unroll 4
            for (int i = 0; i < 16; ++i) {
                int kb = i * 4 + p1_ks;
                const float* wp = wgp + kb * 512;
                ulonglong2 w0 = *(const ulonglong2*)(wp);
                ulonglong2 w1 = *(const ulonglong2*)(wp + 4);
                ulonglong2 w2 = *(const ulonglong2*)(wp + 8);
                ulonglong2 w3 = *(const ulonglong2*)(wp + 12);
                int kk = (kb * 4) ^ p1_swz;
                ulonglong2 h0 = *(const ulonglong2*)(hb + kk);
                ulonglong2 h1 = *(const ulonglong2*)(hb + 256 + kk);
                ulonglong2 h2 = *(const ulonglong2*)(hb + 512 + kk);
                ulonglong2 h3 = *(const ulonglong2*)(hb + 768 + kk);
                a[0]  = fma2(w0.x, h0.x, a[0]);   a[0]  = fma2(w0.y, h0.y, a[0]);
                a[1]  = fma2(w0.x, h1.x, a[1]);   a[1]  = fma2(w0.y, h1.y, a[1]);
                a[2]  = fma2(w0.x, h2.x, a[2]);   a[2]  = fma2(w0.y, h2.y, a[2]);
                a[3]  = fma2(w0.x, h3.x, a[3]);   a[3]  = fma2(w0.y, h3.y, a[3]);
                a[4]  = fma2(w1.x, h0.x, a[4]);   a[4]  = fma2(w1.y, h0.y, a[4]);
                a[5]  = fma2(w1.x, h1.x, a[5]);   a[5]  = fma2(w1.y, h1.y, a[5]);
                a[6]  = fma2(w1.x, h2.x, a[6]);   a[6]  = fma2(w1.y, h2.y, a[6]);
                a[7]  = fma2(w1.x, h3.x, a[7]);   a[7]  = fma2(w1.y, h3.y, a[7]);
                a[8]  = fma2(w2.x, h0.x, a[8]);   a[8]  = fma2(w2.y, h0.y, a[8]);
                a[9]  = fma2(w2.x, h1.x, a[9]);   a[9]  = fma2(w2.y, h1.y, a[9]);
                a[10] = fma2(w2.x, h2.x, a[10]);  a[10] = fma2(w2.y, h2.y, a[10]);
                a[11] = fma2(w2.x, h3.x, a[11]);  a[11] = fma2(w2.y, h3.y, a[11]);
                a[12] = fma2(w3.x, h0.x, a[12]);  a[12] = fma2(w3.y, h0.y, a[12]);
                a[13] = fma2(w3.x, h1.x, a[13]);  a[13] = fma2(w3.y, h1.y, a[13]);
                a[14] = fma2(w3.x, h2.x, a[14]);  a[14] = fma2(w3.y, h2.y, a[14]);
                a[15] = fma2(w3.x, h3.x, a[15]);  a[15] = fma2(w3.y, h3.y, a[15]);
            }
        }
        // gx loads (latency overlapped by reduction + other warps)
        float gxa[16];
#pragma unroll
        for (int ri = 0; ri < 4; ++ri) {
            float4 g = *(const float4*)(g_Gx +
                ((size_t)(b0 + p1_rg * 4 + ri) * T_ + t) * 512 + gcolb);
            gxa[0 * 4 + ri] = g.x; gxa[1 * 4 + ri] = g.y;
            gxa[2 * 4 + ri] = g.z; gxa[3 * 4 + ri] = g.w;
        }
        // reduce over k-quarters (ks in lane bits [3:5))
        float f[16];
#pragma unroll
        for (int x = 0; x < 16; ++x) { float2 v = unpack2(a[x]); f[x] = v.x + v.y; }
#pragma unroll
        for (int x = 0; x < 16; ++x) f[x] += __shfl_xor_sync(0xffffffffu, f[x], 8);
#pragma unroll
        for (int x = 0; x < 16; ++x) f[x] += __shfl_xor_sync(0xffffffffu, f[x], 16);

        const bool doRH = (p1_ks == 0) && isRw;
        const bool doU  = (p1_ks == 0) && !isRw;
        ull rhlo[4], rhhi[4];
        uint32_t hA1[4];
        if (doRH) {
#pragma unroll
            for (int ri = 0; ri < 4; ++ri) {
                int row = p1_rg * 4 + ri;
                int off = OFF_H + row * 256 + (hcolb ^ p1_swz);
                float4 ho = *(const float4*)(sm + off);
                float r0 = sigmoid_f(f[0 + ri] + gxa[0 + ri])  * ho.x;
                float r1 = sigmoid_f(f[4 + ri] + gxa[4 + ri])  * ho.y;
                float r2 = sigmoid_f(f[8 + ri] + gxa[8 + ri])  * ho.z;
                float r3 = sigmoid_f(f[12 + ri] + gxa[12 + ri]) * ho.w;
                rhlo[ri] = pack2(r0, r1);
                rhhi[ri] = pack2(r2, r3);
                hA1[ri]  = smaddr + (uint32_t)off * 4;
            }
        } else if (doU) {
#pragma unroll
            for (int ci = 0; ci < 4; ++ci) {
                int lc = p1_jb - 64 + ci;
                *(float4*)(sm + OFF_U + lc * 16 + p1_rg * 4) = make_float4(
                    sigmoid_f(f[ci * 4 + 0] + gxa[ci * 4 + 0]),
                    sigmoid_f(f[ci * 4 + 1] + gxa[ci * 4 + 1]),
                    sigmoid_f(f[ci * 4 + 2] + gxa[ci * 4 + 2]),
                    sigmoid_f(f[ci * 4 + 3] + gxa[ci * 4 + 3]));
            }
        }
        // phase-2 output lanes snapshot their hold before the r*h overwrite
        float hold2[16];
        if (isOut) {
#pragma unroll
            for (int ri = 0; ri < 4; ++ri) {
                int row = lane * 4 + ri;
                float4 ho = *(const float4*)(sm + OFF_H + row * 256 + (gc2 ^ (lane << 3)));
                hold2[0 * 4 + ri] = ho.x; hold2[1 * 4 + ri] = ho.y;
                hold2[2 * 4 + ri] = ho.z; hold2[3 * 4 + ri] = ho.w;
            }
        }
        CLUSTER_SYNC();   // all h reads done cluster-wide
        if (doRH) {
#pragma unroll
            for (int ri = 0; ri < 4; ++ri)
#pragma unroll
                for (uint32_t rk = 0; rk < CSZ; ++rk) {
                    uint32_t ra = mapa_sh(hA1[ri], rk);
                    st_cluster_b64(ra, rhlo[ri]);
                    st_cluster_b64(ra + 8, rhhi[ri]);
                }
        }
        CLUSTER_SYNC();   // r*h visible everywhere

        // ================= phase 2 GEMV (candidate) =================
        float cxa[16];
        if (isOut) {
#pragma unroll
            for (int ri = 0; ri < 4; ++ri) {
                float4 g = *(const float4*)(g_Cx +
                    ((size_t)(b0 + lane * 4 + ri) * T_ + t) * 256 + gc2);
                cxa[0 * 4 + ri] = g.x; cxa[1 * 4 + ri] = g.y;
                cxa[2 * 4 + ri] = g.z; cxa[3 * 4 + ri] = g.w;
            }
        }
        ull a2[16];
#pragma unroll
        for (int x = 0; x < 16; ++x) a2[x] = 0ull;
        {
            const float* wcp = sm + OFF_WC + p2_jb * 4;
            const float* hb  = sm + OFF_H + p2_rg * 4 * 256;
#pragma unroll 4
            for (int i = 0; i < 8; ++i) {
                int kb = i * 8 + p2_ks;
                const float* wp = wcp + kb * WCSTR;
                ulonglong2 w0 = *(const ulonglong2*)(wp);
                ulonglong2 w1 = *(const ulonglong2*)(wp + 4);
                ulonglong2 w2 = *(const ulonglong2*)(wp + 8);
                ulonglong2 w3 = *(const ulonglong2*)(wp + 12);
                int kk = (kb * 4) ^ p2_swz;
                ulonglong2 h0 = *(const ulonglong2*)(hb + kk);
                ulonglong2 h1 = *(const ulonglong2*)(hb + 256 + kk);
                ulonglong2 h2 = *(const ulonglong2*)(hb + 512 + kk);
                ulonglong2 h3 = *(const ulonglong2*)(hb + 768 + kk);
                a2[0]  = fma2(w0.x, h0.x, a2[0]);   a2[0]  = fma2(w0.y, h0.y, a2[0]);
                a2[1]  = fma2(w0.x, h1.x, a2[1]);   a2[1]  = fma2(w0.y, h1.y, a2[1]);
                a2[2]  = fma2(w0.x, h2.x, a2[2]);   a2[2]  = fma2(w0.y, h2.y, a2[2]);
                a2[3]  = fma2(w0.x, h3.x, a2[3]);   a2[3]  = fma2(w0.y, h3.y, a2[3]);
                a2[4]  = fma2(w1.x, h0.x, a2[4]);   a2[4]  = fma2(w1.y, h0.y, a2[4]);
                a2[5]  = fma2(w1.x, h1.x, a2[5]);   a2[5]  = fma2(w1.y, h1.y, a2[5]);
                a2[6]  = fma2(w1.x, h2.x, a2[6]);   a2[6]  = fma2(w1.y, h2.y, a2[6]);
                a2[7]  = fma2(w1.x, h3.x, a2[7]);   a2[7]  = fma2(w1.y, h3.y, a2[7]);
                a2[8]  = fma2(w2.x, h0.x, a2[8]);   a2[8]  = fma2(w2.y, h0.y, a2[8]);
                a2[9]  = fma2(w2.x, h1.x, a2[9]);   a2[9]  = fma2(w2.y, h1.y, a2[9]);
                a2[10] = fma2(w2.x, h2.x, a2[10]);  a2[10] = fma2(w2.y, h2.y, a2[10]);
                a2[11] = fma2(w2.x, h3.x, a2[11]);  a2[11] = fma2(w2.y, h3.y, a2[11]);
                a2[12] = fma2(w3.x, h0.x, a2[12]);  a2[12] = fma2(w3.y, h0.y, a2[12]);
                a2[13] = fma2(w3.x, h1.x, a2[13]);  a2[13] = fma2(w3.y, h1.y, a2[13]);
                a2[14] = fma2(w3.x, h2.x, a2[14]);  a2[14] = fma2(w3.y, h2.y, a2[14]);
                a2[15] = fma2(w3.x, h3.x, a2[15]);  a2[15] = fma2(w3.y, h3.y, a2[15]);
            }
        }
        float f2[16];
#pragma unroll
        for (int x = 0; x < 16; ++x) { float2 v = unpack2(a2[x]); f2[x] = v.x + v.y; }
#pragma unroll
        for (int x = 0; x < 16; ++x) f2[x] += __shfl_xor_sync(0xffffffffu, f2[x], 4);
#pragma unroll
        for (int x = 0; x < 16; ++x) f2[x] += __shfl_xor_sync(0xffffffffu, f2[x], 8);
#pragma unroll
        for (int x = 0; x < 16; ++x) f2[x] += __shfl_xor_sync(0xffffffffu, f2[x], 16);

        ull hnlo[4], hnhi[4];
        uint32_t hA2[4];
        if (isOut) {
            float ua[16];
#pragma unroll
            for (int ci = 0; ci < 4; ++ci) {
                float4 uq = *(const float4*)(sm + OFF_U + (p2_jb + ci) * 16 + lane * 4);
                ua[ci * 4 + 0] = uq.x; ua[ci * 4 + 1] = uq.y;
                ua[ci * 4 + 2] = uq.z; ua[ci * 4 + 3] = uq.w;
            }
#pragma unroll
            for (int ri = 0; ri < 4; ++ri) {
                int row = lane * 4 + ri;
                bool valid = (t < lenv[ri]);
                float hn[4], ov[4];
#pragma unroll
                for (int ci = 0; ci < 4; ++ci) {
                    float cc = tanh_f(f2[ci * 4 + ri] + cxa[ci * 4 + ri]);
                    float uu = ua[ci * 4 + ri];
                    float ho = hold2[ci * 4 + ri];
                    float nh = uu * ho + (1.f - uu) * cc;
                    hn[ci] = valid ? nh : ho;
                    ov[ci] = valid ? nh : 0.f;
                }
                *(float4*)(out + ((size_t)(b0 + row) * T_ + t) * 256 + gc2) =
                    make_float4(ov[0], ov[1], ov[2], ov[3]);
                hnlo[ri] = pack2(hn[0], hn[1]);
                hnhi[ri] = pack2(hn[2], hn[3]);
                hA2[ri]  = smaddr +
                    (uint32_t)(OFF_H + row * 256 + (gc2 ^ (lane << 3))) * 4;
            }
        }
        CLUSTER_SYNC();   // all r*h reads done
        if (isOut) {
#pragma unroll
            for (int ri = 0; ri < 4; ++ri)
#pragma unroll
                for (uint32_t rk = 0; rk < CSZ; ++rk) {
                    uint32_t ra = mapa_sh(hA2[ri], rk);
                    st_cluster_b64(ra, hnlo[ri]);
                    st_cluster_b64(ra + 8, hnhi[ri]);
                }
        }
        CLUSTER_SYNC();   // new h visible everywhere
    }

    // zero-fill tail t in [tmax, 200): CTA c covers rows [c*4, c*4+4)
    for (int t = tmax; t < T_; ++t) {
#pragma unroll
        for (int w = 0; w < 2; ++w) {
            int cell = w * 512 + tid;            // 0..1023
            int row  = (int)c * 4 + (cell >> 8);
            int col  = cell & 255;
            out[((size_t)(b0 + row) * T_ + t) * 256 + col] = 0.f;
        }
    }
}

// ---------------------------------------------------------------------------
extern "C" void kernel_launch(void* const* d_in, const int* in_sizes, int n_in,
                              void* d_out, int out_size)
{
    const float* X  = (const float*)d_in[0];   // [512, 200, 256]
    const int*   L  = (const int*)  d_in[1];   // [512, 1]
    const float* Wg = (const float*)d_in[2];   // [512, 512]
    const float* bg = (const float*)d_in[3];   // [512]
    const float* Wc = (const float*)d_in[4];   // [512, 256]
    const float* bc = (const float*)d_in[5];   // [256]
    float* out = (float*)d_out;                // [512, 200, 256]

    // Input projections (parallel, independent of recurrence)
    gemm_precompute<<<dim3(BT_ / GBM, (2 * H_) / GBN), 256>>>(X, Wg, bg, L, 2 * H_);
    gemm_precompute<<<dim3(BT_ / GBM, H_ / GBN),       256>>>(X, Wc, bc, L, H_);

    // Sequential scan: 32 clusters x 4 CTAs, SMEM-resident weights
    cudaFuncSetAttribute(gru_recurrent,
                         cudaFuncAttributeMaxDynamicSharedMemorySize, SMEM_BYTES);
    gru_recurrent<<<NG_ * CSZ, THREADS_R, SMEM_BYTES>>>(Wg, Wc, L, out);
}

// round 9
// speedup vs baseline: 1.6415x; 1.6415x over previous
#include <cuda_runtime.h>
#include <math.h>
#include <stdint.h>

// Problem constants
#define B_   512
#define T_   200
#define D_   256
#define H_   256
#define BT_  (B_ * T_)      // 102400

// Recurrent-kernel geometry
#define RG_  16             // batch rows per cluster
#define NG_  (B_ / RG_)     // 32 clusters
#define CSZ  4              // CTAs per cluster (column split)
#define THREADS_R 512

typedef unsigned long long ull;

// Scratch (device globals; no allocation anywhere)
__device__ float g_Gx[BT_ * 2 * H_];   // [B*T, 512]  x@Wgx + gate_bias
__device__ float g_Cx[BT_ * H_];       // [B*T, 256]  x@Wcx + cand_bias

// SMEM layout (float offsets)
#define OFF_WG 0            // [64 kb][128 jcol][4 k]: jcol<64 r-cols, >=64 u-cols (128 KB)
#define OFF_WC 32768        // [64 kb][64 j][4 k] cand weights (64 KB)
#define OFF_H  49152        // h[row 16][k 256], XOR-swizzled (16 KB)
#define OFF_RH 53248        // r*h[row 16][k 256], same layout (16 KB)
#define SMEM_FLOATS 57344
#define SMEM_BYTES (SMEM_FLOATS * 4)   // 229376 B  (< 232448 max)

// h swizzle: row group (row>>2) XORs k by {0,8,16,24} floats so the 4 rows
// read in one LSU phase land in disjoint bank quartets. Self-inverse;
// 4-aligned k chunks stay contiguous.
__device__ __forceinline__ int hoff(int row, int k) {
    return row * 256 + (k ^ (((row >> 2) & 3) << 3));
}

// ---- Blackwell packed fp32x2 helpers ----
__device__ __forceinline__ ull fma2(ull a, ull b, ull c) {
    ull d; asm("fma.rn.f32x2 %0, %1, %2, %3;" : "=l"(d) : "l"(a), "l"(b), "l"(c));
    return d;
}
__device__ __forceinline__ ull pack2(float lo, float hi) {
    ull d; asm("mov.b64 %0, {%1, %2};" : "=l"(d) : "f"(lo), "f"(hi));
    return d;
}
__device__ __forceinline__ float2 unpack2(ull v) {
    float2 r; asm("mov.b64 {%0, %1}, %2;" : "=f"(r.x), "=f"(r.y) : "l"(v));
    return r;
}
__device__ __forceinline__ float sigmoid_f(float x) { return 1.f / (1.f + __expf(-x)); }
__device__ __forceinline__ float tanh_f(float x)    { return 2.f / (1.f + __expf(-2.f * x)) - 1.f; }

__device__ __forceinline__ uint32_t smem_u32(const void* p) {
    uint32_t a;
    asm("{ .reg .u64 t; cvta.to.shared.u64 t, %1; cvt.u32.u64 %0, t; }" : "=r"(a) : "l"(p));
    return a;
}
__device__ __forceinline__ uint32_t ctarank() {
    uint32_t r; asm("mov.u32 %0, %%cluster_ctarank;" : "=r"(r));
    return r;
}
__device__ __forceinline__ uint32_t mapa_sh(uint32_t addr, uint32_t rank) {
    uint32_t r; asm("mapa.shared::cluster.u32 %0, %1, %2;" : "=r"(r) : "r"(addr), "r"(rank));
    return r;
}
__device__ __forceinline__ void st_cluster_b32(uint32_t addr, float v) {
    asm volatile("st.shared::cluster.b32 [%0], %1;" :: "r"(addr), "f"(v) : "memory");
}
#define CLUSTER_SYNC() do { \
    asm volatile("barrier.cluster.arrive.aligned;" ::: "memory"); \
    asm volatile("barrier.cluster.wait.aligned;" ::: "memory");   \
} while (0)

// ---------------------------------------------------------------------------
// Precompute GEMM (unchanged)
// ---------------------------------------------------------------------------
#define GBM 128
#define GBN 64
#define GBK 16

__global__ __launch_bounds__(256) void gemm_precompute(
    const float* __restrict__ X,
    const float* __restrict__ W,
    const float* __restrict__ bias,
    const int*   __restrict__ seqlen,
    int N)
{
    const int r0 = blockIdx.x * GBM;
    const int n0 = blockIdx.y * GBN;

    {
        int b0 = r0 / T_;
        int b1 = (r0 + GBM - 1) / T_;
        bool needed = false;
        for (int b = b0; b <= b1; ++b) {
            int tstart = r0 - b * T_;
            if (tstart < 0) tstart = 0;
            if (tstart < seqlen[b]) { needed = true; break; }
        }
        if (!needed) return;
    }

    float* __restrict__ C = (N == 2 * H_) ? g_Gx : g_Cx;

    __shared__ float As[GBK][GBM];
    __shared__ float Bs[GBK][GBN];

    const int tid = threadIdx.x;
    const int am  = tid >> 2;
    const int ak  = (tid & 3) * 4;
    const int bk  = tid >> 4;
    const int bn  = (tid & 15) * 4;
    const int tm  = (tid >> 4) * 8;
    const int tn  = (tid & 15) * 4;

    ull acc2[4][4];
#pragma unroll
    for (int p = 0; p < 4; ++p)
#pragma unroll
        for (int j = 0; j < 4; ++j) acc2[p][j] = 0ull;

    for (int kt = 0; kt < D_; kt += GBK) {
        float4 a0 = *(const float4*)(X + (size_t)(r0 + am) * D_ + kt + ak);
        float4 a1 = *(const float4*)(X + (size_t)(r0 + am + 64) * D_ + kt + ak);
        As[ak + 0][am] = a0.x;  As[ak + 1][am] = a0.y;
        As[ak + 2][am] = a0.z;  As[ak + 3][am] = a0.w;
        As[ak + 0][am + 64] = a1.x;  As[ak + 1][am + 64] = a1.y;
        As[ak + 2][am + 64] = a1.z;  As[ak + 3][am + 64] = a1.w;
        *(float4*)&Bs[bk][bn] = *(const float4*)(W + (size_t)(kt + bk) * N + n0 + bn);
        __syncthreads();

#pragma unroll
        for (int k = 0; k < GBK; ++k) {
            ulonglong2 a01 = *(const ulonglong2*)&As[k][tm];
            ulonglong2 a23 = *(const ulonglong2*)&As[k][tm + 4];
            float4 bq = *(const float4*)&Bs[k][tn];
            ull ap[4] = { a01.x, a01.y, a23.x, a23.y };
            ull bp[4] = { pack2(bq.x, bq.x), pack2(bq.y, bq.y),
                          pack2(bq.z, bq.z), pack2(bq.w, bq.w) };
#pragma unroll
            for (int p = 0; p < 4; ++p)
#pragma unroll
                for (int j = 0; j < 4; ++j)
                    acc2[p][j] = fma2(ap[p], bp[j], acc2[p][j]);
        }
        __syncthreads();
    }

    float4 bv = *(const float4*)(bias + n0 + tn);
#pragma unroll
    for (int p = 0; p < 4; ++p) {
        float2 c0 = unpack2(acc2[p][0]);
        float2 c1 = unpack2(acc2[p][1]);
        float2 c2 = unpack2(acc2[p][2]);
        float2 c3 = unpack2(acc2[p][3]);
        int row0 = r0 + tm + 2 * p;
        float4 o0 = make_float4(c0.x + bv.x, c1.x + bv.y, c2.x + bv.z, c3.x + bv.w);
        float4 o1 = make_float4(c0.y + bv.x, c1.y + bv.y, c2.y + bv.z, c3.y + bv.w);
        *(float4*)(C + (size_t)row0 * N + n0 + tn) = o0;
        *(float4*)(C + (size_t)(row0 + 1) * N + n0 + tn) = o1;
    }
}

// ---------------------------------------------------------------------------
// Recurrent kernel: 32 clusters x 4 CTAs, 16 batch rows/cluster, weights in
// SMEM (round-6 GEMV loops). New structure: r*h goes to a SEPARATE RH buffer
// and h_new is written by the u-warps (which hold u and a pre-sync snapshot
// of hold in registers) -> only TWO cluster barriers per step:
//   [all warps GEMV1 over H] [r: write RH remote | u: snapshot hold]
//   SYNC A   (RH visible; all H reads done)
//   [u-warps: GEMV2 over RH, blend, write out, write H remote]
//   SYNC B   (H visible; all RH reads done)
// ---------------------------------------------------------------------------
__global__ __launch_bounds__(THREADS_R, 1) __cluster_dims__(CSZ, 1, 1)
void gru_recurrent(const float* __restrict__ Wg,   // [512, 512]
                   const float* __restrict__ Wc,   // [512, 256]
                   const int*   __restrict__ seqlen,
                   float* __restrict__ out)        // [B, T, 256]
{
    extern __shared__ float sm[];
    const int tid = threadIdx.x;
    const uint32_t c = ctarank();
    const int b0   = (blockIdx.x / CSZ) * RG_;
    const int jcol = tid >> 2;          // 0..127
    const int rg   = tid & 3;
    const int rbase = rg * 4;
    const bool isR = (jcol < 64);
    const int jc   = isR ? jcol : (jcol - 64);

    // ---- load weight slices into SMEM ----
    for (int idx = tid; idx < 64 * 128; idx += THREADS_R) {
        int kb = idx >> 7, jj = idx & 127;
        int col = (jj < 64) ? ((int)c * 64 + jj) : (256 + (int)c * 64 + (jj - 64));
#pragma unroll
        for (int i = 0; i < 4; ++i)
            sm[OFF_WG + kb * 512 + jj * 4 + i] = Wg[(256 + kb * 4 + i) * 512 + col];
    }
    for (int idx = tid; idx < 64 * 64; idx += THREADS_R) {
        int kb = idx >> 6, jj = idx & 63;
        int col = (int)c * 64 + jj;
#pragma unroll
        for (int i = 0; i < 4; ++i)
            sm[OFF_WC + kb * 256 + jj * 4 + i] = Wc[(256 + kb * 4 + i) * 256 + col];
    }
    for (int i = tid; i < 16 * 256; i += THREADS_R) sm[OFF_H + i] = 0.f;

    int tmax = 0;
    for (int rr = 0; rr < RG_; ++rr) tmax = max(tmax, seqlen[b0 + rr]);
    int len[4];
#pragma unroll
    for (int rr = 0; rr < 4; ++rr) len[rr] = seqlen[b0 + rbase + rr];

    __syncthreads();
    CLUSTER_SYNC();

    const uint32_t smaddr = smem_u32(sm);
    const int gcol = isR ? ((int)c * 64 + jc) : (256 + (int)c * 64 + jc);
    const int ccol = (int)c * 64 + jc;
    const float* __restrict__ wg = sm + OFF_WG + jcol * 4;
    const float* __restrict__ wc = sm + OFF_WC + jc * 4;

    for (int t = 0; t < tmax; ++t) {
        // hoisted global loads (latency covered by GEMV1)
        float gx[4];
#pragma unroll
        for (int rr = 0; rr < 4; ++rr)
            gx[rr] = g_Gx[((size_t)(b0 + rbase + rr) * T_ + t) * 512 + gcol];
        float cx[4];
        if (!isR) {
#pragma unroll
            for (int rr = 0; rr < 4; ++rr)
                cx[rr] = g_Cx[((size_t)(b0 + rbase + rr) * T_ + t) * 256 + ccol];
        }

        // -------- phase 1 GEMV: one gate column x 4 rows over k=256 --------
        ull a[4] = {0, 0, 0, 0};
#pragma unroll 4
        for (int kb = 0; kb < 64; ++kb) {
            ulonglong2 wv = *(const ulonglong2*)(wg + kb * 512);
#pragma unroll
            for (int rr = 0; rr < 4; ++rr) {
                ulonglong2 hv = *(const ulonglong2*)(sm + OFF_H + hoff(rbase + rr, kb * 4));
                a[rr] = fma2(wv.x, hv.x, a[rr]);
                a[rr] = fma2(wv.y, hv.y, a[rr]);
            }
        }
        float gate[4], hold[4];
#pragma unroll
        for (int rr = 0; rr < 4; ++rr) {
            float2 s = unpack2(a[rr]);
            gate[rr] = sigmoid_f(s.x + s.y + gx[rr]);
            hold[rr] = sm[OFF_H + hoff(rbase + rr, ccol)];
        }
        if (isR) {
            // write r*h into RH of all 4 CTAs (RH's prior readers finished
            // before last step's SYNC B, so no barrier needed before writing)
#pragma unroll
            for (int rr = 0; rr < 4; ++rr) {
                float rh = gate[rr] * hold[rr];
                uint32_t la = smaddr +
                    (uint32_t)(OFF_RH + hoff(rbase + rr, ccol)) * 4;
#pragma unroll
                for (uint32_t rk = 0; rk < CSZ; ++rk)
                    st_cluster_b32(mapa_sh(la, rk), rh);
            }
        }
        CLUSTER_SYNC();   // A: RH complete everywhere; all H reads done

        // -------- phase 2 (u-warps): c = tanh(Cx + RH@Wch); blend ----------
        if (!isR) {
            ull acd[4] = {0, 0, 0, 0};
#pragma unroll 4
            for (int kb = 0; kb < 64; ++kb) {
                ulonglong2 wv = *(const ulonglong2*)(wc + kb * 256);
#pragma unroll
                for (int rr = 0; rr < 4; ++rr) {
                    ulonglong2 hv = *(const ulonglong2*)(sm + OFF_RH + hoff(rbase + rr, kb * 4));
                    acd[rr] = fma2(wv.x, hv.x, acd[rr]);
                    acd[rr] = fma2(wv.y, hv.y, acd[rr]);
                }
            }
#pragma unroll
            for (int rr = 0; rr < 4; ++rr) {
                float2 s = unpack2(acd[rr]);
                float cc = tanh_f(s.x + s.y + cx[rr]);
                float uu = gate[rr];                 // u lives in registers
                float nh = uu * hold[rr] + (1.f - uu) * cc;
                bool valid = (t < len[rr]);
                float hw = valid ? nh : hold[rr];
                out[((size_t)(b0 + rbase + rr) * T_ + t) * 256 + ccol] =
                    valid ? nh : 0.f;
                uint32_t la = smaddr +
                    (uint32_t)(OFF_H + hoff(rbase + rr, ccol)) * 4;
#pragma unroll
                for (uint32_t rk = 0; rk < CSZ; ++rk)
                    st_cluster_b32(mapa_sh(la, rk), hw);
            }
        }
        CLUSTER_SYNC();   // B: new h complete everywhere; RH reads done
    }

    // zero-fill tail t in [tmax, 200): CTA c covers rows [c*4, c*4+4)
    for (int t = tmax; t < T_; ++t) {
#pragma unroll
        for (int w = 0; w < 2; ++w) {
            int cell = w * 512 + tid;            // 0..1023
            int row  = (int)c * 4 + (cell >> 8);
            int col  = cell & 255;
            out[((size_t)(b0 + row) * T_ + t) * 256 + col] = 0.f;
        }
    }
}

// ---------------------------------------------------------------------------
extern "C" void kernel_launch(void* const* d_in, const int* in_sizes, int n_in,
                              void* d_out, int out_size)
{
    const float* X  = (const float*)d_in[0];   // [512, 200, 256]
    const int*   L  = (const int*)  d_in[1];   // [512, 1]
    const float* Wg = (const float*)d_in[2];   // [512, 512]
    const float* bg = (const float*)d_in[3];   // [512]
    const float* Wc = (const float*)d_in[4];   // [512, 256]
    const float* bc = (const float*)d_in[5];   // [256]
    float* out = (float*)d_out;                // [512, 200, 256]

    // Input projections (parallel, independent of recurrence)
    gemm_precompute<<<dim3(BT_ / GBM, (2 * H_) / GBN), 256>>>(X, Wg, bg, L, 2 * H_);
    gemm_precompute<<<dim3(BT_ / GBM, H_ / GBN),       256>>>(X, Wc, bc, L, H_);

    // Sequential scan: 32 clusters x 4 CTAs, SMEM-resident weights
    cudaFuncSetAttribute(gru_recurrent,
                         cudaFuncAttributeMaxDynamicSharedMemorySize, SMEM_BYTES);
    gru_recurrent<<<NG_ * CSZ, THREADS_R, SMEM_BYTES>>>(Wg, Wc, L, out);
}